// round 6
// baseline (speedup 1.0000x reference)
#include <cuda_runtime.h>

#define BB 64
#define WW 128
#define FF 64
#define OUTF 64
#define CH 128
#define TI 32
#define PARTN (BB * WW * OUTF)

typedef unsigned long long ull;

// Scratch: projected features (with bias), per-head partial outputs
__device__ float g_fsrc[BB * WW * CH];
__device__ float g_fdst[BB * WW * CH];
__device__ float g_part[2 * PARTN];

// ---- packed f32x2 helpers ----
__device__ __forceinline__ ull fma2(ull a, ull b, ull c) {
    ull d; asm("fma.rn.f32x2 %0, %1, %2, %3;" : "=l"(d) : "l"(a), "l"(b), "l"(c)); return d;
}
__device__ __forceinline__ ull add2(ull a, ull b) {
    ull d; asm("add.rn.f32x2 %0, %1, %2;" : "=l"(d) : "l"(a), "l"(b)); return d;
}
__device__ __forceinline__ ull dup2(float a) {
    ull d; asm("mov.b64 %0, {%1, %1};" : "=l"(d) : "f"(a)); return d;
}
__device__ __forceinline__ float lo2(ull v) { return __uint_as_float((unsigned)(v & 0xffffffffu)); }
__device__ __forceinline__ float hi2(ull v) { return __uint_as_float((unsigned)(v >> 32)); }
__device__ __forceinline__ float hsum2(ull v) { return lo2(v) + hi2(v); }
#define ABSMASK 0x7fffffff7fffffffULL

// 16B-chunk swizzle within a 64-float (16-chunk) row
__device__ __forceinline__ int swz16(int row, int c) { return (c & 8) | ((c ^ row) & 7); }

// ---------------------------------------------------------------------------
// Kernel 1: projections. C[8192 x 256] = X[8192 x 64] @ W^T + bias.
// grid (4, 64): bx = (src/dst, col-half), by = 128-row tile. 256 threads.
// Thread tile 8 rows x 4 cols; f32x2 packed over f. Dynamic smem 51KB.
// ---------------------------------------------------------------------------
#define PROJ_SM_BYTES ((128 * 68 + 64 * 68) * 4)

__global__ __launch_bounds__(256, 2) void proj_kernel(
    const float* __restrict__ x,
    const float* __restrict__ w_src, const float* __restrict__ b_src,
    const float* __restrict__ w_dst, const float* __restrict__ b_dst)
{
    extern __shared__ float psm[];
    float* xs = psm;                 // 128 x 68
    float* ws = psm + 128 * 68;      // 64 x 68

    const int tid = threadIdx.x;
    const int ot = blockIdx.x;           // 0..3
    const int row0 = blockIdx.y * 128;
    const bool is_src = (ot < 2);
    const float* __restrict__ wm = is_src ? w_src : w_dst;
    const float* __restrict__ bv = is_src ? b_src : b_dst;
    const int obase = (ot & 1) * 64;

    const float4* __restrict__ x4 = (const float4*)(x + row0 * FF);
    const float4* __restrict__ w4 = (const float4*)(wm + obase * FF);
    #pragma unroll
    for (int t = 0; t < 8; t++) {        // 2048 float4 of x
        int m = tid + 256 * t;
        int r = m >> 4, c4 = m & 15;
        *(float4*)(xs + r * 68 + c4 * 4) = x4[m];
    }
    #pragma unroll
    for (int t = 0; t < 4; t++) {        // 1024 float4 of w
        int m = tid + 256 * t;
        int r = m >> 4, c4 = m & 15;
        *(float4*)(ws + r * 68 + c4 * 4) = w4[m];
    }
    __syncthreads();

    const int cx = tid & 15;    // col group (4 cols, stride 16)
    const int ry = tid >> 4;    // row group (8 rows, stride 16)

    ull acc[8][4];
    #pragma unroll
    for (int r = 0; r < 8; r++)
        #pragma unroll
        for (int c = 0; c < 4; c++) acc[r][c] = 0ULL;

    const ulonglong2* __restrict__ xs16 = (const ulonglong2*)xs;
    const ulonglong2* __restrict__ ws16 = (const ulonglong2*)ws;

    #pragma unroll 4
    for (int f4 = 0; f4 < 16; f4++) {
        ulonglong2 wv[4];
        #pragma unroll
        for (int c = 0; c < 4; c++) wv[c] = ws16[(cx + 16 * c) * 17 + f4];
        // rows in two batches of 4 to bound register pressure
        #pragma unroll
        for (int rb = 0; rb < 2; rb++) {
            ulonglong2 xr[4];
            #pragma unroll
            for (int r = 0; r < 4; r++)
                xr[r] = xs16[(ry + 16 * (rb * 4 + r)) * 17 + f4];
            #pragma unroll
            for (int r = 0; r < 4; r++)
                #pragma unroll
                for (int c = 0; c < 4; c++) {
                    acc[rb * 4 + r][c] = fma2(xr[r].x, wv[c].x, acc[rb * 4 + r][c]);
                    acc[rb * 4 + r][c] = fma2(xr[r].y, wv[c].y, acc[rb * 4 + r][c]);
                }
        }
    }

    float* __restrict__ dst = is_src ? g_fsrc : g_fdst;
    #pragma unroll
    for (int c = 0; c < 4; c++) {
        int oloc = obase + cx + 16 * c;
        float bias = bv[oloc];
        #pragma unroll
        for (int r = 0; r < 8; r++) {
            int bw = row0 + ry + 16 * r;
            dst[bw * CH + oloc] = hsum2(acc[r][c]) + bias;
        }
    }
}

// ---------------------------------------------------------------------------
// Kernel 2: attention, HEAD-SPLIT, TI=32. grid (4 i-tiles, 64 b, 2 h).
// 256 threads, 3 blocks/SM. Warp owns 4 full i-rows -> in-warp softmax.
// smem (floats):
//   fsrc_h [128 x 64]  swizzled 16B chunks       0 .. 8192
//   fdst_h [32 x 68]   padded                 8192 .. 10368
//   alpha2 [32 x 128]  DUP f32 pairs         10368 .. 18560  (reused as red)
//   a04    [64]                              18560 .. 18624
//   sA     [128]                             18624 .. 18752  (1.5-prescaled)
//   dA     [32]                              18752 .. 18784
// ---------------------------------------------------------------------------
#define OFF_FDST  8192
#define OFF_ALPHA 10368
#define OFF_A04   18560
#define OFF_SA    18624
#define OFF_DA    18752
#define SM_FLOATS 18784
#define SM_BYTES  (SM_FLOATS * 4)

__global__ __launch_bounds__(256, 3) void attn_kernel(const float* __restrict__ attn_w)
{
    extern __shared__ float sm[];
    float* fsrc_sm = sm;
    float* fdst_sm = sm + OFF_FDST;
    ull*   alpha2  = (ull*)(sm + OFF_ALPHA);
    float* a04     = sm + OFF_A04;
    float* sA      = sm + OFF_SA;
    float* dA      = sm + OFF_DA;

    const int tid = threadIdx.x;
    const int b  = blockIdx.y;
    const int i0 = blockIdx.x * TI;
    const int h  = blockIdx.z;

    ulonglong2* fs16 = (ulonglong2*)fsrc_sm;

    // ---- fill fsrc_h: 128 rows x 16 chunks (swizzled, STS.128) ----
    {
        const float4* __restrict__ g4 = (const float4*)(g_fsrc + b * WW * CH + h * 64);
        #pragma unroll
        for (int t = 0; t < 8; t++) {
            int m = tid + 256 * t;           // 2048 chunks
            int j = m >> 4, c = m & 15;
            float4 v = g4[j * 32 + c];
            *(float4*)(fsrc_sm + j * 64 + swz16(j, c) * 4) = v;
        }
    }
    // ---- fill fdst_h tile: 32 rows x 16 chunks, padded stride 68 ----
    {
        const float4* __restrict__ g4 = (const float4*)(g_fdst + (b * WW + i0) * CH + h * 64);
        #pragma unroll
        for (int t = 0; t < 2; t++) {
            int m = tid + 256 * t;           // 512 chunks
            int i = m >> 4, c = m & 15;
            *(float4*)(fdst_sm + i * 68 + c * 4) = g4[i * 32 + c];
        }
    }
    if (tid < 64) a04[tid] = 0.4f * attn_w[h * 64 + tid];
    __syncthreads();

    // ---- per-node dots (1.5-prescaled linear leakyrelu component) ----
    if (tid < 128) {               // sA[j]
        int j = tid;
        const ulonglong2* a16 = (const ulonglong2*)a04;
        ull acc = 0ULL;
        #pragma unroll
        for (int f4 = 0; f4 < 16; f4++) {
            ulonglong2 sv = fs16[j * 16 + swz16(j, f4)];
            ulonglong2 av = a16[f4];
            acc = fma2(av.x, sv.x, acc);
            acc = fma2(av.y, sv.y, acc);
        }
        sA[j] = 1.5f * hsum2(acc);
    } else if (tid < 160) {        // dA[i], one warp
        int il = tid - 128;
        const ulonglong2* d16 = (const ulonglong2*)(fdst_sm + il * 68);
        const ulonglong2* a16 = (const ulonglong2*)a04;
        ull acc = 0ULL;
        #pragma unroll
        for (int f4 = 0; f4 < 16; f4++) {
            ulonglong2 dv = d16[f4];
            ulonglong2 av = a16[f4];
            acc = fma2(av.x, dv.x, acc);
            acc = fma2(av.y, dv.y, acc);
        }
        dA[il] = 1.5f * hsum2(acc);
    }
    __syncthreads();

    // ---- score: warp w owns rows {w+8r, r<4}; lanes jt; j = jt + 32c ----
    const int jt = tid & 31;
    const int w  = tid >> 5;

    ull acc2[4][4];
    #pragma unroll
    for (int r = 0; r < 4; r++)
        #pragma unroll
        for (int c = 0; c < 4; c++) acc2[r][c] = 0ULL;

    {
        const ulonglong2* a16 = (const ulonglong2*)a04;
        #pragma unroll 4
        for (int f4 = 0; f4 < 16; f4++) {
            ulonglong2 av = a16[f4];
            ulonglong2 dv[4], sv[4];
            #pragma unroll
            for (int r = 0; r < 4; r++)   // broadcast loads (warp-uniform addr)
                dv[r] = *(const ulonglong2*)(fdst_sm + (w + 8 * r) * 68 + f4 * 4);
            int cs = swz16(jt, f4);
            #pragma unroll
            for (int c = 0; c < 4; c++)
                sv[c] = fs16[(jt + 32 * c) * 16 + cs];
            #pragma unroll
            for (int r = 0; r < 4; r++)
                #pragma unroll
                for (int c = 0; c < 4; c++) {
                    ull t0 = add2(sv[c].x, dv[r].x) & ABSMASK;
                    acc2[r][c] = fma2(av.x, t0, acc2[r][c]);
                    ull t1 = add2(sv[c].y, dv[r].y) & ABSMASK;
                    acc2[r][c] = fma2(av.y, t1, acc2[r][c]);
                }
        }
    }

    // ---- softmax over j (in-warp), write DUPLICATED alpha pairs ----
    {
        float sAv[4];
        #pragma unroll
        for (int c = 0; c < 4; c++) sAv[c] = sA[jt + 32 * c];

        #pragma unroll
        for (int r = 0; r < 4; r++) {
            int il = w + 8 * r;
            float dv = dA[il];
            float e[4];
            #pragma unroll
            for (int c = 0; c < 4; c++)
                e[c] = sAv[c] + dv + hsum2(acc2[r][c]);

            float m = fmaxf(fmaxf(e[0], e[1]), fmaxf(e[2], e[3]));
            #pragma unroll
            for (int off = 16; off > 0; off >>= 1)
                m = fmaxf(m, __shfl_xor_sync(0xffffffffu, m, off));

            float p[4], ssum = 0.0f;
            #pragma unroll
            for (int c = 0; c < 4; c++) { p[c] = __expf(e[c] - m); ssum += p[c]; }
            #pragma unroll
            for (int off = 16; off > 0; off >>= 1)
                ssum += __shfl_xor_sync(0xffffffffu, ssum, off);

            float inv = 1.0f / ssum;
            #pragma unroll
            for (int c = 0; c < 4; c++)
                alpha2[il * WW + jt + 32 * c] = dup2(p[c] * inv);
        }
    }
    __syncthreads();

    // ---- aggregation: js = j-quarter, ig -> rows {ig+4k, k<8}, fg = 4-float
    const int fg = tid & 15;
    const int ig = (tid >> 4) & 3;
    const int js = tid >> 6;

    ull accA[8][2];
    #pragma unroll
    for (int k = 0; k < 8; k++) { accA[k][0] = 0ULL; accA[k][1] = 0ULL; }

    {
        const ulonglong2* A2 = (const ulonglong2*)alpha2;   // [row][64 j-pairs]
        #pragma unroll 2
        for (int jp = 0; jp < 16; jp++) {
            int jp2 = js * 16 + jp;
            int ja = 2 * jp2, jb = ja + 1;
            ulonglong2 s0 = fs16[ja * 16 + swz16(ja, fg)];
            ulonglong2 s1 = fs16[jb * 16 + swz16(jb, fg)];
            #pragma unroll
            for (int k = 0; k < 8; k++) {
                ulonglong2 al = A2[(ig + 4 * k) * 64 + jp2];
                accA[k][0] = fma2(al.x, s0.x, accA[k][0]);
                accA[k][1] = fma2(al.x, s0.y, accA[k][1]);
                accA[k][0] = fma2(al.y, s1.x, accA[k][0]);
                accA[k][1] = fma2(al.y, s1.y, accA[k][1]);
            }
        }
    }

    // ---- cross-quarter reduction (scratch reuses alpha region) + STG ----
    __syncthreads();                    // all alpha/fsrc reads done
    {
        ull* red = (ull*)alpha2;        // 4096 ull; need 192*17 = 3264
        const int t64 = tid & 63;
        if (js > 0) {
            int base = ((js - 1) * 64 + t64) * 17;
            #pragma unroll
            for (int k = 0; k < 8; k++) {
                red[base + 2 * k]     = accA[k][0];
                red[base + 2 * k + 1] = accA[k][1];
            }
        }
        __syncthreads();
        if (js == 0) {
            float* part = g_part + h * PARTN;
            #pragma unroll
            for (int q = 1; q < 4; q++) {
                const ull* rr = red + ((q - 1) * 64 + t64) * 17;
                #pragma unroll
                for (int k = 0; k < 8; k++) {
                    accA[k][0] = add2(accA[k][0], rr[2 * k]);
                    accA[k][1] = add2(accA[k][1], rr[2 * k + 1]);
                }
            }
            #pragma unroll
            for (int k = 0; k < 8; k++) {
                int i = i0 + ig + 4 * k;
                float4 o;
                o.x = lo2(accA[k][0]); o.y = hi2(accA[k][0]);
                o.z = lo2(accA[k][1]); o.w = hi2(accA[k][1]);
                *(float4*)(part + (b * WW + i) * OUTF + fg * 4) = o;
            }
        }
    }
}

// ---------------------------------------------------------------------------
// Kernel 3: combine heads. out = 0.5 * (part0 + part1). 512 x 256 float4.
// ---------------------------------------------------------------------------
__global__ __launch_bounds__(256) void combine_kernel(float* __restrict__ out)
{
    int m = blockIdx.x * 256 + threadIdx.x;
    const float4* p0 = (const float4*)g_part;
    const float4* p1 = (const float4*)(g_part + PARTN);
    float4 a = p0[m], c = p1[m];
    float4 o;
    o.x = 0.5f * (a.x + c.x);
    o.y = 0.5f * (a.y + c.y);
    o.z = 0.5f * (a.z + c.z);
    o.w = 0.5f * (a.w + c.w);
    ((float4*)out)[m] = o;
}

// ---------------------------------------------------------------------------
extern "C" void kernel_launch(void* const* d_in, const int* in_sizes, int n_in,
                              void* d_out, int out_size)
{
    (void)in_sizes; (void)n_in; (void)out_size;
    const float* x      = (const float*)d_in[0];
    const float* w_src  = (const float*)d_in[1];
    const float* b_src  = (const float*)d_in[2];
    const float* w_dst  = (const float*)d_in[3];
    const float* b_dst  = (const float*)d_in[4];
    const float* attn_w = (const float*)d_in[5];
    float* out = (float*)d_out;

    cudaFuncSetAttribute(proj_kernel,
                         cudaFuncAttributeMaxDynamicSharedMemorySize,
                         PROJ_SM_BYTES);
    cudaFuncSetAttribute(attn_kernel,
                         cudaFuncAttributeMaxDynamicSharedMemorySize,
                         SM_BYTES);

    proj_kernel<<<dim3(4, 64), 256, PROJ_SM_BYTES>>>(x, w_src, b_src, w_dst, b_dst);
    attn_kernel<<<dim3(WW / TI, BB, 2), 256, SM_BYTES>>>(attn_w);
    combine_kernel<<<512, 256>>>(out);
}

// round 7
// speedup vs baseline: 1.1164x; 1.1164x over previous
#include <cuda_runtime.h>

#define BB 64
#define WW 128
#define FF 64
#define OUTF 64
#define CH 128
#define TI 16
#define PARTN (BB * WW * OUTF)

typedef unsigned long long ull;

// Scratch: projected features (with bias), per-head partial outputs
__device__ float g_fsrc[BB * WW * CH];
__device__ float g_fdst[BB * WW * CH];
__device__ float g_part[2 * PARTN];

// ---- packed f32x2 helpers ----
__device__ __forceinline__ ull fma2(ull a, ull b, ull c) {
    ull d; asm("fma.rn.f32x2 %0, %1, %2, %3;" : "=l"(d) : "l"(a), "l"(b), "l"(c)); return d;
}
__device__ __forceinline__ ull add2(ull a, ull b) {
    ull d; asm("add.rn.f32x2 %0, %1, %2;" : "=l"(d) : "l"(a), "l"(b)); return d;
}
__device__ __forceinline__ ull dup2(float a) {
    ull d; asm("mov.b64 %0, {%1, %1};" : "=l"(d) : "f"(a)); return d;
}
__device__ __forceinline__ float lo2(ull v) { return __uint_as_float((unsigned)(v & 0xffffffffu)); }
__device__ __forceinline__ float hi2(ull v) { return __uint_as_float((unsigned)(v >> 32)); }
__device__ __forceinline__ float hsum2(ull v) { return lo2(v) + hi2(v); }
#define ABSMASK 0x7fffffff7fffffffULL

// 16B-chunk swizzle within a 64-float (16-chunk) row
__device__ __forceinline__ int swz16(int row, int c) { return (c & 8) | ((c ^ row) & 7); }

__device__ __forceinline__ unsigned to_tf32(float v) {
    unsigned o; asm("cvt.rna.tf32.f32 %0, %1;" : "=r"(o) : "f"(v)); return o;
}

// ---------------------------------------------------------------------------
// Kernel 1: projections via tf32 tensor cores.
// C[8192 x 256] = X[8192 x 64] @ W^T + bias.
// grid (4, 64): bx = (src/dst, 64-col half), by = 128-row tile. 256 thr.
// Warp w computes m-rows [w*16, w*16+16) x all 64 cols, k = 64.
// mma.sync.m16n8k8.row.col.f32.tf32.tf32.f32
// ---------------------------------------------------------------------------
#define PROJ_SM_BYTES ((128 * 68 + 64 * 68) * 4)

__global__ __launch_bounds__(256, 4) void proj_kernel(
    const float* __restrict__ x,
    const float* __restrict__ w_src, const float* __restrict__ b_src,
    const float* __restrict__ w_dst, const float* __restrict__ b_dst)
{
    extern __shared__ unsigned psm[];
    unsigned* xs = psm;                 // 128 x 68  (tf32 bits)
    unsigned* ws = psm + 128 * 68;      // 64 x 68

    const int tid = threadIdx.x;
    const int ot = blockIdx.x;           // 0..3
    const int row0 = blockIdx.y * 128;
    const bool is_src = (ot < 2);
    const float* __restrict__ wm = is_src ? w_src : w_dst;
    const float* __restrict__ bv = is_src ? b_src : b_dst;
    const int obase = (ot & 1) * 64;

    // ---- fill (convert to tf32 once) ----
    const float4* __restrict__ x4 = (const float4*)(x + row0 * FF);
    const float4* __restrict__ w4 = (const float4*)(wm + obase * FF);
    #pragma unroll
    for (int t = 0; t < 8; t++) {        // 2048 float4 of x
        int m = tid + 256 * t;
        int r = m >> 4, c4 = m & 15;
        float4 v = x4[m];
        uint4 u;
        u.x = to_tf32(v.x); u.y = to_tf32(v.y);
        u.z = to_tf32(v.z); u.w = to_tf32(v.w);
        *(uint4*)(xs + r * 68 + c4 * 4) = u;
    }
    #pragma unroll
    for (int t = 0; t < 4; t++) {        // 1024 float4 of w
        int m = tid + 256 * t;
        int r = m >> 4, c4 = m & 15;
        float4 v = w4[m];
        uint4 u;
        u.x = to_tf32(v.x); u.y = to_tf32(v.y);
        u.z = to_tf32(v.z); u.w = to_tf32(v.w);
        *(uint4*)(ws + r * 68 + c4 * 4) = u;
    }
    __syncthreads();

    const int w    = tid >> 5;
    const int lane = tid & 31;
    const int ly = lane >> 2;     // 0..7
    const int lx = lane & 3;      // 0..3
    const int m0 = w * 16;

    float acc[8][4];
    #pragma unroll
    for (int t = 0; t < 8; t++)
        #pragma unroll
        for (int q = 0; q < 4; q++) acc[t][q] = 0.0f;

    #pragma unroll
    for (int k0 = 0; k0 < 64; k0 += 8) {
        unsigned a0 = xs[(m0 + ly) * 68 + k0 + lx];
        unsigned a1 = xs[(m0 + ly + 8) * 68 + k0 + lx];
        unsigned a2 = xs[(m0 + ly) * 68 + k0 + lx + 4];
        unsigned a3 = xs[(m0 + ly + 8) * 68 + k0 + lx + 4];
        #pragma unroll
        for (int t = 0; t < 8; t++) {
            unsigned b0 = ws[(t * 8 + ly) * 68 + k0 + lx];
            unsigned b1 = ws[(t * 8 + ly) * 68 + k0 + lx + 4];
            asm("mma.sync.aligned.m16n8k8.row.col.f32.tf32.tf32.f32 "
                "{%0,%1,%2,%3}, {%4,%5,%6,%7}, {%8,%9}, {%0,%1,%2,%3};"
                : "+f"(acc[t][0]), "+f"(acc[t][1]), "+f"(acc[t][2]), "+f"(acc[t][3])
                : "r"(a0), "r"(a1), "r"(a2), "r"(a3), "r"(b0), "r"(b1));
        }
    }

    // ---- epilogue: bias + store (STG.64 pairs) ----
    float* __restrict__ dst = is_src ? g_fsrc : g_fdst;
    #pragma unroll
    for (int t = 0; t < 8; t++) {
        int cb = t * 8 + 2 * lx;                 // local col (pair base)
        float2 bias = *(const float2*)(bv + obase + cb);
        int rA = row0 + m0 + ly;
        float2 oA = make_float2(acc[t][0] + bias.x, acc[t][1] + bias.y);
        float2 oB = make_float2(acc[t][2] + bias.x, acc[t][3] + bias.y);
        *(float2*)(dst + rA * CH + obase + cb) = oA;
        *(float2*)(dst + (rA + 8) * CH + obase + cb) = oB;
    }
}

// ---------------------------------------------------------------------------
// Kernel 2: attention, HEAD-SPLIT. grid (8 i-tiles, 64 b, 2 h), 256 threads.
// Score/softmax: warp owns 2 rows, in-warp softmax.
// Aggregation: j-quarter split, 4-f-wide threads, plain STG epilogue.
// smem (floats):
//   fsrc_h [128 x 64]  swizzled 16B chunks       0 .. 8192
//   fdst_h [16 x 68]   padded                 8192 .. 9280
//   alpha2 [16 x 128]  DUP f32 pairs          9280 .. 13376  (reused as red)
//   a04    [64]                              13376 .. 13440
//   sA     [128]                             13440 .. 13568  (1.5-prescaled)
//   dA     [16]                              13568 .. 13584
// ---------------------------------------------------------------------------
#define OFF_FDST  8192
#define OFF_ALPHA 9280
#define OFF_A04   13376
#define OFF_SA    13440
#define OFF_DA    13568
#define SM_FLOATS 13584
#define SM_BYTES  (SM_FLOATS * 4)

__global__ __launch_bounds__(256, 4) void attn_kernel(const float* __restrict__ attn_w)
{
    extern __shared__ float sm[];
    float* fsrc_sm = sm;
    float* fdst_sm = sm + OFF_FDST;
    ull*   alpha2  = (ull*)(sm + OFF_ALPHA);
    float* a04     = sm + OFF_A04;
    float* sA      = sm + OFF_SA;
    float* dA      = sm + OFF_DA;

    const int tid = threadIdx.x;
    const int b  = blockIdx.y;
    const int i0 = blockIdx.x * TI;
    const int h  = blockIdx.z;

    ulonglong2* fs16 = (ulonglong2*)fsrc_sm;

    // ---- fill fsrc_h: 128 rows x 16 chunks (swizzled, STS.128) ----
    {
        const float4* __restrict__ g4 = (const float4*)(g_fsrc + b * WW * CH + h * 64);
        #pragma unroll
        for (int t = 0; t < 8; t++) {
            int m = tid + 256 * t;           // 2048 chunks
            int j = m >> 4, c = m & 15;
            float4 v = g4[j * 32 + c];
            *(float4*)(fsrc_sm + j * 64 + swz16(j, c) * 4) = v;
        }
    }
    // ---- fill fdst_h tile: 16 rows x 16 chunks, padded stride 68 ----
    {
        const float4* __restrict__ g4 = (const float4*)(g_fdst + (b * WW + i0) * CH + h * 64);
        int i = tid >> 4, c = tid & 15;
        *(float4*)(fdst_sm + i * 68 + c * 4) = g4[i * 32 + c];
    }
    if (tid < 64) a04[tid] = 0.4f * attn_w[h * 64 + tid];
    __syncthreads();

    // ---- per-node dots (1.5-prescaled linear leakyrelu component) ----
    if (tid < 128) {               // sA[j]
        int j = tid;
        const ulonglong2* a16 = (const ulonglong2*)a04;
        ull acc = 0ULL;
        #pragma unroll
        for (int f4 = 0; f4 < 16; f4++) {
            ulonglong2 sv = fs16[j * 16 + swz16(j, f4)];
            ulonglong2 av = a16[f4];
            acc = fma2(av.x, sv.x, acc);
            acc = fma2(av.y, sv.y, acc);
        }
        sA[j] = 1.5f * hsum2(acc);
    } else if (tid < 144) {        // dA[i]
        int il = tid - 128;
        const ulonglong2* d16 = (const ulonglong2*)(fdst_sm + il * 68);
        const ulonglong2* a16 = (const ulonglong2*)a04;
        ull acc = 0ULL;
        #pragma unroll
        for (int f4 = 0; f4 < 16; f4++) {
            ulonglong2 dv = d16[f4];
            ulonglong2 av = a16[f4];
            acc = fma2(av.x, dv.x, acc);
            acc = fma2(av.y, dv.y, acc);
        }
        dA[il] = 1.5f * hsum2(acc);
    }
    __syncthreads();

    // ---- score: warp w owns i rows {w, w+8}; lanes jt; j = jt + 32c ----
    const int jt = tid & 31;
    const int w  = tid >> 5;

    ull acc2[2][4];
    #pragma unroll
    for (int r = 0; r < 2; r++)
        #pragma unroll
        for (int c = 0; c < 4; c++) acc2[r][c] = 0ULL;

    {
        const ulonglong2* a16 = (const ulonglong2*)a04;
        #pragma unroll 4
        for (int f4 = 0; f4 < 16; f4++) {
            ulonglong2 av = a16[f4];
            ulonglong2 dv[2], sv[4];
            dv[0] = *(const ulonglong2*)(fdst_sm + w * 68 + f4 * 4);
            dv[1] = *(const ulonglong2*)(fdst_sm + (w + 8) * 68 + f4 * 4);
            int cs = swz16(jt, f4);
            #pragma unroll
            for (int c = 0; c < 4; c++)
                sv[c] = fs16[(jt + 32 * c) * 16 + cs];
            #pragma unroll
            for (int r = 0; r < 2; r++)
                #pragma unroll
                for (int c = 0; c < 4; c++) {
                    ull t0 = add2(sv[c].x, dv[r].x) & ABSMASK;
                    acc2[r][c] = fma2(av.x, t0, acc2[r][c]);
                    ull t1 = add2(sv[c].y, dv[r].y) & ABSMASK;
                    acc2[r][c] = fma2(av.y, t1, acc2[r][c]);
                }
        }
    }

    // ---- softmax over j (in-warp), write DUPLICATED alpha pairs ----
    {
        float sAv[4];
        #pragma unroll
        for (int c = 0; c < 4; c++) sAv[c] = sA[jt + 32 * c];

        #pragma unroll
        for (int r = 0; r < 2; r++) {
            int il = w + 8 * r;
            float dv = dA[il];
            float e[4];
            #pragma unroll
            for (int c = 0; c < 4; c++)
                e[c] = sAv[c] + dv + hsum2(acc2[r][c]);

            float m = fmaxf(fmaxf(e[0], e[1]), fmaxf(e[2], e[3]));
            #pragma unroll
            for (int off = 16; off > 0; off >>= 1)
                m = fmaxf(m, __shfl_xor_sync(0xffffffffu, m, off));

            float p[4], ssum = 0.0f;
            #pragma unroll
            for (int c = 0; c < 4; c++) { p[c] = __expf(e[c] - m); ssum += p[c]; }
            #pragma unroll
            for (int off = 16; off > 0; off >>= 1)
                ssum += __shfl_xor_sync(0xffffffffu, ssum, off);

            float inv = 1.0f / ssum;
            #pragma unroll
            for (int c = 0; c < 4; c++)
                alpha2[il * WW + jt + 32 * c] = dup2(p[c] * inv);
        }
    }
    __syncthreads();

    // ---- aggregation: js = j-quarter, ig -> i rows {ig+4k}, fg = 4-float group
    const int fg = tid & 15;
    const int ig = (tid >> 4) & 3;
    const int js = tid >> 6;

    ull accA[4][2];
    #pragma unroll
    for (int k = 0; k < 4; k++) { accA[k][0] = 0ULL; accA[k][1] = 0ULL; }

    {
        const ulonglong2* A2 = (const ulonglong2*)alpha2;   // [row][64 j-pairs]
        #pragma unroll 4
        for (int jp = 0; jp < 16; jp++) {
            int jp2 = js * 16 + jp;
            int ja = 2 * jp2, jb = ja + 1;
            ulonglong2 al[4];
            #pragma unroll
            for (int k = 0; k < 4; k++)
                al[k] = A2[(ig + 4 * k) * 64 + jp2];        // 2 addrs/warp
            ulonglong2 s0 = fs16[ja * 16 + swz16(ja, fg)];  // 4 floats of row ja
            ulonglong2 s1 = fs16[jb * 16 + swz16(jb, fg)];
            #pragma unroll
            for (int k = 0; k < 4; k++) {
                accA[k][0] = fma2(al[k].x, s0.x, accA[k][0]);
                accA[k][1] = fma2(al[k].x, s0.y, accA[k][1]);
                accA[k][0] = fma2(al[k].y, s1.x, accA[k][0]);
                accA[k][1] = fma2(al[k].y, s1.y, accA[k][1]);
            }
        }
    }

    // ---- cross-quarter reduction (scratch reuses alpha region) + STG ----
    __syncthreads();                    // all alpha/fsrc reads done
    {
        ull* red = (ull*)alpha2;        // 2048 ull available; need 192*9=1728
        const int t64 = tid & 63;
        if (js > 0) {
            int base = ((js - 1) * 64 + t64) * 9;   // stride 9 -> low conflict
            #pragma unroll
            for (int k = 0; k < 4; k++) {
                red[base + 2 * k]     = accA[k][0];
                red[base + 2 * k + 1] = accA[k][1];
            }
        }
        __syncthreads();
        if (js == 0) {
            float* part = g_part + h * PARTN;
            #pragma unroll
            for (int q = 1; q < 4; q++) {
                const ull* rr = red + ((q - 1) * 64 + t64) * 9;
                #pragma unroll
                for (int k = 0; k < 4; k++) {
                    accA[k][0] = add2(accA[k][0], rr[2 * k]);
                    accA[k][1] = add2(accA[k][1], rr[2 * k + 1]);
                }
            }
            #pragma unroll
            for (int k = 0; k < 4; k++) {
                int i = i0 + ig + 4 * k;
                float4 o;
                o.x = lo2(accA[k][0]); o.y = hi2(accA[k][0]);
                o.z = lo2(accA[k][1]); o.w = hi2(accA[k][1]);
                *(float4*)(part + (b * WW + i) * OUTF + fg * 4) = o;
            }
        }
    }
}

// ---------------------------------------------------------------------------
// Kernel 3: combine heads. out = 0.5 * (part0 + part1). 512 x 256 float4.
// ---------------------------------------------------------------------------
__global__ __launch_bounds__(256) void combine_kernel(float* __restrict__ out)
{
    int m = blockIdx.x * 256 + threadIdx.x;
    const float4* p0 = (const float4*)g_part;
    const float4* p1 = (const float4*)(g_part + PARTN);
    float4 a = p0[m], c = p1[m];
    float4 o;
    o.x = 0.5f * (a.x + c.x);
    o.y = 0.5f * (a.y + c.y);
    o.z = 0.5f * (a.z + c.z);
    o.w = 0.5f * (a.w + c.w);
    ((float4*)out)[m] = o;
}

// ---------------------------------------------------------------------------
extern "C" void kernel_launch(void* const* d_in, const int* in_sizes, int n_in,
                              void* d_out, int out_size)
{
    (void)in_sizes; (void)n_in; (void)out_size;
    const float* x      = (const float*)d_in[0];
    const float* w_src  = (const float*)d_in[1];
    const float* b_src  = (const float*)d_in[2];
    const float* w_dst  = (const float*)d_in[3];
    const float* b_dst  = (const float*)d_in[4];
    const float* attn_w = (const float*)d_in[5];
    float* out = (float*)d_out;

    cudaFuncSetAttribute(proj_kernel,
                         cudaFuncAttributeMaxDynamicSharedMemorySize,
                         PROJ_SM_BYTES);
    cudaFuncSetAttribute(attn_kernel,
                         cudaFuncAttributeMaxDynamicSharedMemorySize,
                         SM_BYTES);

    proj_kernel<<<dim3(4, 64), 256, PROJ_SM_BYTES>>>(x, w_src, b_src, w_dst, b_dst);
    attn_kernel<<<dim3(WW / TI, BB, 2), 256, SM_BYTES>>>(attn_w);
    combine_kernel<<<512, 256>>>(out);
}